// round 14
// baseline (speedup 1.0000x reference)
#include <cuda_runtime.h>
#include <cuda_fp16.h>
#include <math.h>
#include <stdint.h>

// Problem: b=2, s=2048, d=2048, H=16, Dh=128, window=2048 (never binds -> causal)
#define GM 4096
#define GD 2048
#define SEQ 2048
#define NH 16
#define DH 128

// Q is pre-scaled by SM_SCALE*log2(e); softmax runs in exp2 domain.
#define QSCALE (0.08838834764831845f * 1.4426950408889634f)

// ---------------- scratch (device globals; allocation forbidden) ----------------
__device__ __half g_xh[GM * GD];
__device__ __half g_ch[GM * GD];
__device__ __half g_qh[GM * GD];
__device__ __half g_kh[GM * GD];
__device__ __half g_vh[GM * GD];
__device__ __half g_wq[GD * GD], g_wk[GD * GD], g_wv[GD * GD], g_wo[GD * GD];

// ---------------- PTX helpers (compute_103-safe) ----------------
__device__ __forceinline__ uint32_t smem_u32(const void* p) {
    uint32_t a;
    asm("{ .reg .u64 t; cvta.to.shared.u64 t, %1; cvt.u32.u64 %0, t; }" : "=r"(a) : "l"(p));
    return a;
}
#define CP_ASYNC16(dst, src) \
    asm volatile("cp.async.cg.shared.global [%0], [%1], 16;" :: "r"(dst), "l"(src))
#define CP_COMMIT() asm volatile("cp.async.commit_group;" ::: "memory")
#define CP_WAIT(n)  asm volatile("cp.async.wait_group %0;" :: "n"(n) : "memory")

#define LDSM4(r0, r1, r2, r3, addr) \
    asm volatile("ldmatrix.sync.aligned.m8n8.x4.shared.b16 {%0,%1,%2,%3}, [%4];" \
                 : "=r"(r0), "=r"(r1), "=r"(r2), "=r"(r3) : "r"(addr))
#define LDSM4T(r0, r1, r2, r3, addr) \
    asm volatile("ldmatrix.sync.aligned.m8n8.x4.trans.shared.b16 {%0,%1,%2,%3}, [%4];" \
                 : "=r"(r0), "=r"(r1), "=r"(r2), "=r"(r3) : "r"(addr))

#define MMA_F16(d, a, b0, b1)                                               \
    asm volatile(                                                           \
        "mma.sync.aligned.m16n8k16.row.col.f32.f16.f16.f32 "                \
        "{%0,%1,%2,%3}, {%4,%5,%6,%7}, {%8,%9}, {%0,%1,%2,%3};"             \
        : "+f"(d[0]), "+f"(d[1]), "+f"(d[2]), "+f"(d[3])                    \
        : "r"(a[0]), "r"(a[1]), "r"(a[2]), "r"(a[3]), "r"(b0), "r"(b1))

__device__ __forceinline__ uint32_t pack_h2(__half a, __half b) {
    __half2 t = __halves2half2(a, b);
    return *reinterpret_cast<uint32_t*>(&t);
}

// ---------------------------------------------------------------------------
// Merged prep kernel: z = 0..3 -> transpose+fp16 convert weight z;
//                     z = 4    -> elementwise fp16 convert of x.
// ---------------------------------------------------------------------------
__global__ void prep_all(const float* __restrict__ x, __half* __restrict__ xh,
                         const float* __restrict__ W0, const float* __restrict__ W1,
                         const float* __restrict__ W2, const float* __restrict__ W3,
                         __half* __restrict__ a0, __half* __restrict__ a1,
                         __half* __restrict__ a2, __half* __restrict__ a3)
{
    const int z = blockIdx.z;
    if (z == 4) {
        int blk = blockIdx.y * 64 + blockIdx.x;
        int tid = threadIdx.y * 32 + threadIdx.x;
#pragma unroll
        for (int i = 0; i < 2; i++) {
            int idx = (blk * 512) + tid + i * 256;
            float4 v = reinterpret_cast<const float4*>(x)[idx];
            __half2* p = reinterpret_cast<__half2*>(xh) + 2 * idx;
            p[0] = __halves2half2(__float2half_rn(v.x), __float2half_rn(v.y));
            p[1] = __halves2half2(__float2half_rn(v.z), __float2half_rn(v.w));
        }
        return;
    }
    const float* W = (z == 0) ? W0 : (z == 1) ? W1 : (z == 2) ? W2 : W3;
    __half* o = (z == 0) ? a0 : (z == 1) ? a1 : (z == 2) ? a2 : a3;

    __shared__ float t[32][33];
    const int bx = blockIdx.x * 32;
    const int by = blockIdx.y * 32;
    const int tx = threadIdx.x, ty = threadIdx.y;
#pragma unroll
    for (int i = 0; i < 4; i++)
        t[ty + 8 * i][tx] = W[(size_t)(by + ty + 8 * i) * GD + bx + tx];
    __syncthreads();
#pragma unroll
    for (int i = 0; i < 4; i++)
        o[(size_t)(bx + ty + 8 * i) * GD + by + tx] = __float2half_rn(t[tx][ty + 8 * i]);
}

// ---------------------------------------------------------------------------
// Single-term fp16 GEMM, v2: 128x256 CTA tile, 8 warps (2m x 4n),
// warp tile 64x64 (acc 128 regs). smem traffic/MAC cut 31% vs 128x128.
// KT=64; stage = A(16KB)+B(32KB) = 48KB; 3 stages = 144KB; 1 CTA/SM.
// ---------------------------------------------------------------------------
#define KT 64
#define NCH (GD / KT)          // 32
#define TILE_A_B 16384         // 128 rows * 128 bytes
#define TILE_B_B 32768         // 256 rows * 128 bytes
#define STAGE_B (TILE_A_B + TILE_B_B)
#define GEMM_SMEM (3 * STAGE_B)

__device__ __forceinline__ void gemm_body(
    const __half* __restrict__ A1, const __half* __restrict__ B1,
    float* __restrict__ Cf, __half* __restrict__ O1,
    float oscale, uint32_t sbase, int m0, int n0)
{
    const int tid  = threadIdx.x;
    const int lane = tid & 31;
    const int warp = tid >> 5;
    const int wm = (warp & 1) * 64;    // 0 or 64
    const int wn = (warp >> 1) * 64;   // 0..192

    auto load_stage = [&](int ch, int s) {
        const int k0 = ch * KT;
        const uint32_t stage = sbase + s * STAGE_B;
        const __half* Ag = A1 + (size_t)m0 * GD + k0;
#pragma unroll
        for (int i = 0; i < 4; i++) {                 // A: 128x64 = 1024 chunks
            int idx = tid + i * 256;
            int r = idx >> 3, c = idx & 7;
            uint32_t dst = stage + r * 128 + ((c ^ (r & 7)) << 4);
            CP_ASYNC16(dst, Ag + (size_t)r * GD + c * 8);
        }
        const __half* Bg = B1 + (size_t)n0 * GD + k0;
#pragma unroll
        for (int i = 0; i < 8; i++) {                 // B: 256x64 = 2048 chunks
            int idx = tid + i * 256;
            int r = idx >> 3, c = idx & 7;
            uint32_t dst = stage + TILE_A_B + r * 128 + ((c ^ (r & 7)) << 4);
            CP_ASYNC16(dst, Bg + (size_t)r * GD + c * 8);
        }
        CP_COMMIT();
    };

    float acc[4][8][4];
#pragma unroll
    for (int mt = 0; mt < 4; mt++)
#pragma unroll
        for (int nt = 0; nt < 8; nt++)
#pragma unroll
            for (int r = 0; r < 4; r++) acc[mt][nt][r] = 0.0f;

    load_stage(0, 0);
    load_stage(1, 1);

    for (int ch = 0; ch < NCH; ch++) {
        const int s = ch % 3;
        if (ch + 2 < NCH) { load_stage(ch + 2, (ch + 2) % 3); CP_WAIT(2); }
        else if (ch + 1 < NCH) { CP_WAIT(1); }
        else { CP_WAIT(0); }
        __syncthreads();

        const uint32_t stage = sbase + s * STAGE_B;
#pragma unroll
        for (int ks = 0; ks < 4; ks++) {
            const int chunk = 2 * ks + (lane >> 4);
            uint32_t a1[4][4];
#pragma unroll
            for (int mt = 0; mt < 4; mt++) {
                int row = wm + mt * 16 + (lane & 15);
                LDSM4(a1[mt][0], a1[mt][1], a1[mt][2], a1[mt][3],
                      stage + row * 128 + ((chunk ^ (row & 7)) << 4));
            }
            uint32_t b[8][2];
#pragma unroll
            for (int np = 0; np < 4; np++) {
                int row = wn + np * 16 + (lane & 15);
                uint32_t r0, r1, r2, r3;
                LDSM4(r0, r1, r2, r3,
                      stage + TILE_A_B + row * 128 + ((chunk ^ (row & 7)) << 4));
                b[2 * np][0] = r0; b[2 * np][1] = r2;
                b[2 * np + 1][0] = r1; b[2 * np + 1][1] = r3;
            }
#pragma unroll
            for (int mt = 0; mt < 4; mt++)
#pragma unroll
                for (int nt = 0; nt < 8; nt++)
                    MMA_F16(acc[mt][nt], a1[mt], b[nt][0], b[nt][1]);
        }
        __syncthreads();
    }

    const int gid = lane >> 2, tig = lane & 3;
#pragma unroll
    for (int mt = 0; mt < 4; mt++)
#pragma unroll
        for (int nt = 0; nt < 8; nt++) {
            int row = m0 + wm + mt * 16 + gid;
            int col = n0 + wn + nt * 8 + tig * 2;
            if (O1) {
                uint32_t h0 = pack_h2(__float2half_rn(acc[mt][nt][0] * oscale),
                                      __float2half_rn(acc[mt][nt][1] * oscale));
                uint32_t h1 = pack_h2(__float2half_rn(acc[mt][nt][2] * oscale),
                                      __float2half_rn(acc[mt][nt][3] * oscale));
                *reinterpret_cast<uint32_t*>(&O1[(size_t)row * GD + col]) = h0;
                *reinterpret_cast<uint32_t*>(&O1[(size_t)(row + 8) * GD + col]) = h1;
            } else {
                *reinterpret_cast<float2*>(&Cf[(size_t)row * GD + col]) =
                    make_float2(acc[mt][nt][0], acc[mt][nt][1]);
                *reinterpret_cast<float2*>(&Cf[(size_t)(row + 8) * GD + col]) =
                    make_float2(acc[mt][nt][2], acc[mt][nt][3]);
            }
        }
}

// Fused Q/K/V projection: single-term. Q output pre-scaled by QSCALE.
__global__ __launch_bounds__(256, 1) void hgemm_qkv(
    const __half* __restrict__ xh,
    const __half* __restrict__ wq, const __half* __restrict__ wk,
    const __half* __restrict__ wv,
    __half* __restrict__ qh, __half* __restrict__ kh, __half* __restrict__ vh)
{
    extern __shared__ char smem[];
    const int z = blockIdx.z;
    const __half* B1 = (z == 0) ? wq : (z == 1) ? wk : wv;
    __half* O1 = (z == 0) ? qh : (z == 1) ? kh : vh;
    float oscale = (z == 0) ? QSCALE : 1.0f;
    gemm_body(xh, B1, nullptr, O1, oscale,
              smem_u32(smem), blockIdx.y * 128, blockIdx.x * 256);
}

// Output projection: single-term, fp32 result.
__global__ __launch_bounds__(256, 1) void hgemm_out(
    const __half* __restrict__ ch, const __half* __restrict__ wo,
    float* __restrict__ Cf)
{
    extern __shared__ char smem[];
    gemm_body(ch, wo, Cf, nullptr, 1.0f,
              smem_u32(smem), blockIdx.y * 128, blockIdx.x * 256);
}

// ---------------------------------------------------------------------------
// Flash attention (round-13 proven, unchanged): all-fp16 operands, exp2
// softmax, double-buffered K/V with early prefetch, heavy q-tiles first.
// ---------------------------------------------------------------------------
#define FT_TILE 32768
#define FT_SMEM (5 * FT_TILE)

__device__ __forceinline__ uint32_t ft_addr(uint32_t sb, int tile, int r, int c) {
    return sb + tile * FT_TILE + r * 256 + (((c & 8) | ((c ^ (r & 7)) & 7)) << 4);
}

__global__ __launch_bounds__(256, 1) void flash_tc(
    const __half* __restrict__ Qh, const __half* __restrict__ Kh,
    const __half* __restrict__ Vh, __half* __restrict__ C1)
{
    extern __shared__ char smem[];
    const uint32_t sb = smem_u32(smem);

    const int tid = threadIdx.x, lane = tid & 31, warp = tid >> 5;
    const int qt = gridDim.x - 1 - blockIdx.x;
    const int h = blockIdx.y, b = blockIdx.z;
    const int q0 = qt * 128;
    const size_t base = ((size_t)b * SEQ) * GD + (size_t)h * DH;

    auto load_tile = [&](int t, const __half* src, int r0) {
        const __half* g = src + base + (size_t)r0 * GD;
#pragma unroll
        for (int i = 0; i < 8; i++) {
            int idx = tid + i * 256;
            int r = idx >> 4, c = idx & 15;
            CP_ASYNC16(ft_addr(sb, t, r, c), g + (size_t)r * GD + c * 8);
        }
    };

    load_tile(0, Qh, q0);
    load_tile(1, Kh, 0);
    load_tile(3, Vh, 0);
    CP_COMMIT(); CP_WAIT(0); __syncthreads();

    const int gid = lane >> 2, tig = lane & 3;
    const int qw = warp * 16;

    float o[16][4];
#pragma unroll
    for (int nt = 0; nt < 16; nt++)
#pragma unroll
        for (int c = 0; c < 4; c++) o[nt][c] = 0.0f;
    float m[2] = {-1e30f, -1e30f}, l[2] = {0.0f, 0.0f};

    for (int jt = 0; jt <= qt; jt++) {
        const int cur = jt & 1, nxt = cur ^ 1;

        float s[16][4];
#pragma unroll
        for (int nt = 0; nt < 16; nt++)
#pragma unroll
            for (int c = 0; c < 4; c++) s[nt][c] = 0.0f;

#pragma unroll
        for (int kf = 0; kf < 8; kf++) {
            const int ac = 2 * kf + (lane >> 4);
            uint32_t ah[4];
            {
                int r = qw + (lane & 15);
                LDSM4(ah[0], ah[1], ah[2], ah[3], ft_addr(sb, 0, r, ac));
            }
#pragma unroll
            for (int p = 0; p < 4; p++) {
                int r0 = (2 * p) * 16 + (lane & 15);
                int r1 = (2 * p + 1) * 16 + (lane & 15);
                uint32_t h0, h1, h2, h3, i0, i1, i2, i3;
                LDSM4(h0, h1, h2, h3, ft_addr(sb, 1 + cur, r0, ac));
                LDSM4(i0, i1, i2, i3, ft_addr(sb, 1 + cur, r1, ac));
                MMA_F16(s[4 * p],     ah, h0, h2);
                MMA_F16(s[4 * p + 1], ah, h1, h3);
                MMA_F16(s[4 * p + 2], ah, i0, i2);
                MMA_F16(s[4 * p + 3], ah, i1, i3);
            }
        }

        // early prefetch of next K/V (disjoint buffer) — overlaps softmax too
        if (jt < qt) {
            load_tile(1 + nxt, Kh, (jt + 1) * 128);
            load_tile(3 + nxt, Vh, (jt + 1) * 128);
            CP_COMMIT();
        }

        if (jt == qt) {
#pragma unroll
            for (int nt = 0; nt < 16; nt++) {
                int colb = jt * 128 + nt * 8 + 2 * tig;
#pragma unroll
                for (int c = 0; c < 4; c++) {
                    int row = q0 + qw + gid + ((c >= 2) ? 8 : 0);
                    int col = colb + (c & 1);
                    if (col > row) s[nt][c] = -1e30f;
                }
            }
        }

        float mx0 = -1e30f, mx1 = -1e30f;
#pragma unroll
        for (int nt = 0; nt < 16; nt++) {
            mx0 = fmaxf(mx0, fmaxf(s[nt][0], s[nt][1]));
            mx1 = fmaxf(mx1, fmaxf(s[nt][2], s[nt][3]));
        }
#pragma unroll
        for (int off = 1; off <= 2; off <<= 1) {
            mx0 = fmaxf(mx0, __shfl_xor_sync(0xffffffffu, mx0, off, 4));
            mx1 = fmaxf(mx1, __shfl_xor_sync(0xffffffffu, mx1, off, 4));
        }
        float mn0 = fmaxf(m[0], mx0), mn1 = fmaxf(m[1], mx1);
        float cr0 = exp2f(m[0] - mn0), cr1 = exp2f(m[1] - mn1);
        m[0] = mn0; m[1] = mn1;
        float sum0 = 0.0f, sum1 = 0.0f;
#pragma unroll
        for (int nt = 0; nt < 16; nt++) {
            s[nt][0] = exp2f(s[nt][0] - mn0); sum0 += s[nt][0];
            s[nt][1] = exp2f(s[nt][1] - mn0); sum0 += s[nt][1];
            s[nt][2] = exp2f(s[nt][2] - mn1); sum1 += s[nt][2];
            s[nt][3] = exp2f(s[nt][3] - mn1); sum1 += s[nt][3];
        }
#pragma unroll
        for (int off = 1; off <= 2; off <<= 1) {
            sum0 += __shfl_xor_sync(0xffffffffu, sum0, off, 4);
            sum1 += __shfl_xor_sync(0xffffffffu, sum1, off, 4);
        }
        l[0] = l[0] * cr0 + sum0;
        l[1] = l[1] * cr1 + sum1;
#pragma unroll
        for (int nt = 0; nt < 16; nt++) {
            o[nt][0] *= cr0; o[nt][1] *= cr0;
            o[nt][2] *= cr1; o[nt][3] *= cr1;
        }

#pragma unroll
        for (int kf = 0; kf < 8; kf++) {
            uint32_t ph[4];
            ph[0] = pack_h2(__float2half_rn(s[2 * kf][0]),     __float2half_rn(s[2 * kf][1]));
            ph[1] = pack_h2(__float2half_rn(s[2 * kf][2]),     __float2half_rn(s[2 * kf][3]));
            ph[2] = pack_h2(__float2half_rn(s[2 * kf + 1][0]), __float2half_rn(s[2 * kf + 1][1]));
            ph[3] = pack_h2(__float2half_rn(s[2 * kf + 1][2]), __float2half_rn(s[2 * kf + 1][3]));
            int r = kf * 16 + (lane & 15);
#pragma unroll
            for (int p = 0; p < 4; p++) {
                int c0 = 4 * p + (lane >> 4);
                int c1 = 4 * p + 2 + (lane >> 4);
                uint32_t v0, v1, v2, v3, u0, u1, u2, u3;
                LDSM4T(v0, v1, v2, v3, ft_addr(sb, 3 + cur, r, c0));
                LDSM4T(u0, u1, u2, u3, ft_addr(sb, 3 + cur, r, c1));
                MMA_F16(o[4 * p],     ph, v0, v1);
                MMA_F16(o[4 * p + 1], ph, v2, v3);
                MMA_F16(o[4 * p + 2], ph, u0, u1);
                MMA_F16(o[4 * p + 3], ph, u2, u3);
            }
        }

        if (jt < qt) { CP_WAIT(0); __syncthreads(); }
    }

    float inv0 = 1.0f / l[0], inv1 = 1.0f / l[1];
    int row0 = q0 + qw + gid, row1 = row0 + 8;
#pragma unroll
    for (int nt = 0; nt < 16; nt++) {
        int col = nt * 8 + 2 * tig;
        uint32_t h0 = pack_h2(__float2half_rn(o[nt][0] * inv0),
                              __float2half_rn(o[nt][1] * inv0));
        uint32_t h1 = pack_h2(__float2half_rn(o[nt][2] * inv1),
                              __float2half_rn(o[nt][3] * inv1));
        *reinterpret_cast<uint32_t*>(&C1[base + (size_t)row0 * GD + col]) = h0;
        *reinterpret_cast<uint32_t*>(&C1[base + (size_t)row1 * GD + col]) = h1;
    }
}

// ---------------------------------------------------------------------------
extern "C" void kernel_launch(void* const* d_in, const int* in_sizes, int n_in,
                              void* d_out, int out_size)
{
    const float* x  = (const float*)d_in[0];
    const float* Wq = (const float*)d_in[1];
    const float* Wk = (const float*)d_in[2];
    const float* Wv = (const float*)d_in[3];
    const float* Wo = (const float*)d_in[4];

    __half *xh, *ch, *qh, *kh, *vh;
    cudaGetSymbolAddress((void**)&xh, g_xh);
    cudaGetSymbolAddress((void**)&ch, g_ch);
    cudaGetSymbolAddress((void**)&qh, g_qh);
    cudaGetSymbolAddress((void**)&kh, g_kh);
    cudaGetSymbolAddress((void**)&vh, g_vh);

    __half *wq, *wk, *wv, *wo;
    cudaGetSymbolAddress((void**)&wq, g_wq); cudaGetSymbolAddress((void**)&wk, g_wk);
    cudaGetSymbolAddress((void**)&wv, g_wv); cudaGetSymbolAddress((void**)&wo, g_wo);

    cudaFuncSetAttribute(hgemm_qkv, cudaFuncAttributeMaxDynamicSharedMemorySize, GEMM_SMEM);
    cudaFuncSetAttribute(hgemm_out, cudaFuncAttributeMaxDynamicSharedMemorySize, GEMM_SMEM);
    cudaFuncSetAttribute(flash_tc, cudaFuncAttributeMaxDynamicSharedMemorySize, FT_SMEM);

    prep_all<<<dim3(64, 64, 5), dim3(32, 8)>>>(x, xh, Wq, Wk, Wv, Wo, wq, wk, wv, wo);

    dim3 qkv_grid(GD / 256, GM / 128, 3);   // (8, 32, 3)
    hgemm_qkv<<<qkv_grid, 256, GEMM_SMEM>>>(xh, wq, wk, wv, qh, kh, vh);

    flash_tc<<<dim3(SEQ / 128, NH, 2), 256, FT_SMEM>>>(qh, kh, vh, ch);

    dim3 ggrid(GD / 256, GM / 128);         // (8, 32)
    hgemm_out<<<ggrid, 256, GEMM_SMEM>>>(ch, wo, (float*)d_out);
}

// round 16
// speedup vs baseline: 1.0599x; 1.0599x over previous
#include <cuda_runtime.h>
#include <cuda_fp16.h>
#include <math.h>
#include <stdint.h>

// Problem: b=2, s=2048, d=2048, H=16, Dh=128, window=2048 (never binds -> causal)
#define GM 4096
#define GD 2048
#define SEQ 2048
#define NH 16
#define DH 128

// Q is pre-scaled by SM_SCALE*log2(e); softmax runs in exp2 domain.
#define QSCALE (0.08838834764831845f * 1.4426950408889634f)

// ---------------- scratch (device globals; allocation forbidden) ----------------
__device__ __half g_xh[GM * GD];
__device__ __half g_ch[GM * GD];
__device__ __half g_qh[GM * GD];
__device__ __half g_kh[GM * GD];
__device__ __half g_vh[GM * GD];
__device__ __half g_wq[GD * GD], g_wk[GD * GD], g_wv[GD * GD], g_wo[GD * GD];

// ---------------- PTX helpers (compute_103-safe) ----------------
__device__ __forceinline__ uint32_t smem_u32(const void* p) {
    uint32_t a;
    asm("{ .reg .u64 t; cvta.to.shared.u64 t, %1; cvt.u32.u64 %0, t; }" : "=r"(a) : "l"(p));
    return a;
}
#define CP_ASYNC16(dst, src) \
    asm volatile("cp.async.cg.shared.global [%0], [%1], 16;" :: "r"(dst), "l"(src))
#define CP_COMMIT() asm volatile("cp.async.commit_group;" ::: "memory")
#define CP_WAIT(n)  asm volatile("cp.async.wait_group %0;" :: "n"(n) : "memory")

#define LDSM4(r0, r1, r2, r3, addr) \
    asm volatile("ldmatrix.sync.aligned.m8n8.x4.shared.b16 {%0,%1,%2,%3}, [%4];" \
                 : "=r"(r0), "=r"(r1), "=r"(r2), "=r"(r3) : "r"(addr))
#define LDSM4T(r0, r1, r2, r3, addr) \
    asm volatile("ldmatrix.sync.aligned.m8n8.x4.trans.shared.b16 {%0,%1,%2,%3}, [%4];" \
                 : "=r"(r0), "=r"(r1), "=r"(r2), "=r"(r3) : "r"(addr))

#define MMA_F16(d, a, b0, b1)                                               \
    asm volatile(                                                           \
        "mma.sync.aligned.m16n8k16.row.col.f32.f16.f16.f32 "                \
        "{%0,%1,%2,%3}, {%4,%5,%6,%7}, {%8,%9}, {%0,%1,%2,%3};"             \
        : "+f"(d[0]), "+f"(d[1]), "+f"(d[2]), "+f"(d[3])                    \
        : "r"(a[0]), "r"(a[1]), "r"(a[2]), "r"(a[3]), "r"(b0), "r"(b1))

__device__ __forceinline__ uint32_t pack_h2(__half a, __half b) {
    __half2 t = __halves2half2(a, b);
    return *reinterpret_cast<uint32_t*>(&t);
}

// ---------------------------------------------------------------------------
// Merged prep kernel: z = 0..3 -> transpose+fp16 convert weight z;
//                     z = 4    -> elementwise fp16 convert of x.
// ---------------------------------------------------------------------------
__global__ void prep_all(const float* __restrict__ x, __half* __restrict__ xh,
                         const float* __restrict__ W0, const float* __restrict__ W1,
                         const float* __restrict__ W2, const float* __restrict__ W3,
                         __half* __restrict__ a0, __half* __restrict__ a1,
                         __half* __restrict__ a2, __half* __restrict__ a3)
{
    const int z = blockIdx.z;
    if (z == 4) {
        int blk = blockIdx.y * 64 + blockIdx.x;
        int tid = threadIdx.y * 32 + threadIdx.x;
#pragma unroll
        for (int i = 0; i < 2; i++) {
            int idx = (blk * 512) + tid + i * 256;
            float4 v = reinterpret_cast<const float4*>(x)[idx];
            __half2* p = reinterpret_cast<__half2*>(xh) + 2 * idx;
            p[0] = __halves2half2(__float2half_rn(v.x), __float2half_rn(v.y));
            p[1] = __halves2half2(__float2half_rn(v.z), __float2half_rn(v.w));
        }
        return;
    }
    const float* W = (z == 0) ? W0 : (z == 1) ? W1 : (z == 2) ? W2 : W3;
    __half* o = (z == 0) ? a0 : (z == 1) ? a1 : (z == 2) ? a2 : a3;

    __shared__ float t[32][33];
    const int bx = blockIdx.x * 32;
    const int by = blockIdx.y * 32;
    const int tx = threadIdx.x, ty = threadIdx.y;
#pragma unroll
    for (int i = 0; i < 4; i++)
        t[ty + 8 * i][tx] = W[(size_t)(by + ty + 8 * i) * GD + bx + tx];
    __syncthreads();
#pragma unroll
    for (int i = 0; i < 4; i++)
        o[(size_t)(bx + ty + 8 * i) * GD + by + tx] = __float2half_rn(t[tx][ty + 8 * i]);
}

// ---------------------------------------------------------------------------
// Single-term fp16 GEMM (round-13 proven): 128x128 CTA tile, 256 threads,
// KT=64, 3-stage cp.async pipeline, 96KB smem, 2 CTAs/SM.
// ---------------------------------------------------------------------------
#define KT 64
#define NCH (GD / KT)          // 32
#define TILE_B 16384           // 128 rows * 128 bytes
#define STAGE_B (2 * TILE_B)   // A + B = 32 KB
#define GEMM_SMEM (3 * STAGE_B)

__device__ __forceinline__ void gemm_body(
    const __half* __restrict__ A1, const __half* __restrict__ B1,
    float* __restrict__ Cf, __half* __restrict__ O1,
    float oscale, uint32_t sbase, int m0, int n0)
{
    const int tid  = threadIdx.x;
    const int lane = tid & 31;
    const int warp = tid >> 5;
    const int wm = (warp & 3) * 32;
    const int wn = (warp >> 2) * 64;

    auto load_stage = [&](int ch, int s) {
        const int k0 = ch * KT;
        const uint32_t stage = sbase + s * STAGE_B;
#pragma unroll
        for (int t = 0; t < 2; t++) {
            const __half* gp = (t ? B1 : A1) + (size_t)(t ? n0 : m0) * GD + k0;
#pragma unroll
            for (int i = 0; i < 4; i++) {
                int idx = tid + i * 256;
                int r = idx >> 3, c = idx & 7;
                uint32_t dst = stage + t * TILE_B + r * 128 + ((c ^ (r & 7)) << 4);
                CP_ASYNC16(dst, gp + (size_t)r * GD + c * 8);
            }
        }
        CP_COMMIT();
    };

    float acc[2][8][4];
#pragma unroll
    for (int mt = 0; mt < 2; mt++)
#pragma unroll
        for (int nt = 0; nt < 8; nt++)
#pragma unroll
            for (int r = 0; r < 4; r++) acc[mt][nt][r] = 0.0f;

    load_stage(0, 0);
    load_stage(1, 1);

    for (int ch = 0; ch < NCH; ch++) {
        const int s = ch % 3;
        if (ch + 2 < NCH) { load_stage(ch + 2, (ch + 2) % 3); CP_WAIT(2); }
        else if (ch + 1 < NCH) { CP_WAIT(1); }
        else { CP_WAIT(0); }
        __syncthreads();

        const uint32_t stage = sbase + s * STAGE_B;
#pragma unroll
        for (int ks = 0; ks < 4; ks++) {
            const int chunk = 2 * ks + (lane >> 4);
            uint32_t a1[2][4];
#pragma unroll
            for (int mt = 0; mt < 2; mt++) {
                int row = wm + mt * 16 + (lane & 15);
                LDSM4(a1[mt][0], a1[mt][1], a1[mt][2], a1[mt][3],
                      stage + row * 128 + ((chunk ^ (row & 7)) << 4));
            }
            uint32_t b[8][2];
#pragma unroll
            for (int np = 0; np < 4; np++) {
                int row = wn + np * 16 + (lane & 15);
                uint32_t r0, r1, r2, r3;
                LDSM4(r0, r1, r2, r3,
                      stage + TILE_B + row * 128 + ((chunk ^ (row & 7)) << 4));
                b[2 * np][0] = r0; b[2 * np][1] = r2;
                b[2 * np + 1][0] = r1; b[2 * np + 1][1] = r3;
            }
#pragma unroll
            for (int mt = 0; mt < 2; mt++)
#pragma unroll
                for (int nt = 0; nt < 8; nt++)
                    MMA_F16(acc[mt][nt], a1[mt], b[nt][0], b[nt][1]);
        }
        __syncthreads();
    }

    const int gid = lane >> 2, tig = lane & 3;
#pragma unroll
    for (int mt = 0; mt < 2; mt++)
#pragma unroll
        for (int nt = 0; nt < 8; nt++) {
            int row = m0 + wm + mt * 16 + gid;
            int col = n0 + wn + nt * 8 + tig * 2;
            if (O1) {
                uint32_t h0 = pack_h2(__float2half_rn(acc[mt][nt][0] * oscale),
                                      __float2half_rn(acc[mt][nt][1] * oscale));
                uint32_t h1 = pack_h2(__float2half_rn(acc[mt][nt][2] * oscale),
                                      __float2half_rn(acc[mt][nt][3] * oscale));
                *reinterpret_cast<uint32_t*>(&O1[(size_t)row * GD + col]) = h0;
                *reinterpret_cast<uint32_t*>(&O1[(size_t)(row + 8) * GD + col]) = h1;
            } else {
                *reinterpret_cast<float2*>(&Cf[(size_t)row * GD + col]) =
                    make_float2(acc[mt][nt][0], acc[mt][nt][1]);
                *reinterpret_cast<float2*>(&Cf[(size_t)(row + 8) * GD + col]) =
                    make_float2(acc[mt][nt][2], acc[mt][nt][3]);
            }
        }
}

// Fused Q/K/V projection: single-term. Q output pre-scaled by QSCALE.
__global__ __launch_bounds__(256, 2) void hgemm_qkv(
    const __half* __restrict__ xh,
    const __half* __restrict__ wq, const __half* __restrict__ wk,
    const __half* __restrict__ wv,
    __half* __restrict__ qh, __half* __restrict__ kh, __half* __restrict__ vh)
{
    extern __shared__ char smem[];
    const int z = blockIdx.z;
    const __half* B1 = (z == 0) ? wq : (z == 1) ? wk : wv;
    __half* O1 = (z == 0) ? qh : (z == 1) ? kh : vh;
    float oscale = (z == 0) ? QSCALE : 1.0f;
    gemm_body(xh, B1, nullptr, O1, oscale,
              smem_u32(smem), blockIdx.y * 128, blockIdx.x * 128);
}

// Output projection: single-term, fp32 result.
__global__ __launch_bounds__(256, 2) void hgemm_out(
    const __half* __restrict__ ch, const __half* __restrict__ wo,
    float* __restrict__ Cf)
{
    extern __shared__ char smem[];
    gemm_body(ch, wo, Cf, nullptr, 1.0f,
              smem_u32(smem), blockIdx.y * 128, blockIdx.x * 128);
}

// ---------------------------------------------------------------------------
// Flash attention: round-13 structure + staged K/V prefetch commit groups.
// K(j+1) and V(j+1) are committed as SEPARATE groups after S(j); at the
// iteration boundary we wait only for K (V keeps streaming under S(j+1)),
// and drain V just before PV(j+1).
// smem tiles (32KB): 0 Qh, 1/2 Kh[buf], 3/4 Vh[buf] = 160KB.
// ---------------------------------------------------------------------------
#define FT_TILE 32768
#define FT_SMEM (5 * FT_TILE)

__device__ __forceinline__ uint32_t ft_addr(uint32_t sb, int tile, int r, int c) {
    return sb + tile * FT_TILE + r * 256 + (((c & 8) | ((c ^ (r & 7)) & 7)) << 4);
}

__global__ __launch_bounds__(256, 1) void flash_tc(
    const __half* __restrict__ Qh, const __half* __restrict__ Kh,
    const __half* __restrict__ Vh, __half* __restrict__ C1)
{
    extern __shared__ char smem[];
    const uint32_t sb = smem_u32(smem);

    const int tid = threadIdx.x, lane = tid & 31, warp = tid >> 5;
    const int qt = gridDim.x - 1 - blockIdx.x;   // heavy tiles first
    const int h = blockIdx.y, b = blockIdx.z;
    const int q0 = qt * 128;
    const size_t base = ((size_t)b * SEQ) * GD + (size_t)h * DH;

    auto load_tile = [&](int t, const __half* src, int r0) {
        const __half* g = src + base + (size_t)r0 * GD;
#pragma unroll
        for (int i = 0; i < 8; i++) {
            int idx = tid + i * 256;
            int r = idx >> 4, c = idx & 15;
            CP_ASYNC16(ft_addr(sb, t, r, c), g + (size_t)r * GD + c * 8);
        }
    };

    load_tile(0, Qh, q0);
    load_tile(1, Kh, 0);
    load_tile(3, Vh, 0);
    CP_COMMIT(); CP_WAIT(0); __syncthreads();

    const int gid = lane >> 2, tig = lane & 3;
    const int qw = warp * 16;

    float o[16][4];
#pragma unroll
    for (int nt = 0; nt < 16; nt++)
#pragma unroll
        for (int c = 0; c < 4; c++) o[nt][c] = 0.0f;
    float m[2] = {-1e30f, -1e30f}, l[2] = {0.0f, 0.0f};

    // pending group state: after an iteration with prefetch, 2 groups are in
    // flight (K then V). We wait K at the loop boundary, V before PV.
    bool v_pending = false;

    for (int jt = 0; jt <= qt; jt++) {
        const int cur = jt & 1, nxt = cur ^ 1;

        // ---- S = Q @ K^T (single term) ----
        float s[16][4];
#pragma unroll
        for (int nt = 0; nt < 16; nt++)
#pragma unroll
            for (int c = 0; c < 4; c++) s[nt][c] = 0.0f;

#pragma unroll
        for (int kf = 0; kf < 8; kf++) {
            const int ac = 2 * kf + (lane >> 4);
            uint32_t ah[4];
            {
                int r = qw + (lane & 15);
                LDSM4(ah[0], ah[1], ah[2], ah[3], ft_addr(sb, 0, r, ac));
            }
#pragma unroll
            for (int p = 0; p < 4; p++) {
                int r0 = (2 * p) * 16 + (lane & 15);
                int r1 = (2 * p + 1) * 16 + (lane & 15);
                uint32_t h0, h1, h2, h3, i0, i1, i2, i3;
                LDSM4(h0, h1, h2, h3, ft_addr(sb, 1 + cur, r0, ac));
                LDSM4(i0, i1, i2, i3, ft_addr(sb, 1 + cur, r1, ac));
                MMA_F16(s[4 * p],     ah, h0, h2);
                MMA_F16(s[4 * p + 1], ah, h1, h3);
                MMA_F16(s[4 * p + 2], ah, i0, i2);
                MMA_F16(s[4 * p + 3], ah, i1, i3);
            }
        }

        // early prefetch of next K/V into the other buffer, SEPARATE groups
        const bool prefetched = (jt < qt);
        if (prefetched) {
            load_tile(1 + nxt, Kh, (jt + 1) * 128);
            CP_COMMIT();                             // group: K(j+1)
            load_tile(3 + nxt, Vh, (jt + 1) * 128);
            CP_COMMIT();                             // group: V(j+1)
        }

        // ---- causal mask (diag tile only) ----
        if (jt == qt) {
#pragma unroll
            for (int nt = 0; nt < 16; nt++) {
                int colb = jt * 128 + nt * 8 + 2 * tig;
#pragma unroll
                for (int c = 0; c < 4; c++) {
                    int row = q0 + qw + gid + ((c >= 2) ? 8 : 0);
                    int col = colb + (c & 1);
                    if (col > row) s[nt][c] = -1e30f;
                }
            }
        }

        // ---- online softmax in exp2 domain ----
        float mx0 = -1e30f, mx1 = -1e30f;
#pragma unroll
        for (int nt = 0; nt < 16; nt++) {
            mx0 = fmaxf(mx0, fmaxf(s[nt][0], s[nt][1]));
            mx1 = fmaxf(mx1, fmaxf(s[nt][2], s[nt][3]));
        }
#pragma unroll
        for (int off = 1; off <= 2; off <<= 1) {
            mx0 = fmaxf(mx0, __shfl_xor_sync(0xffffffffu, mx0, off, 4));
            mx1 = fmaxf(mx1, __shfl_xor_sync(0xffffffffu, mx1, off, 4));
        }
        float mn0 = fmaxf(m[0], mx0), mn1 = fmaxf(m[1], mx1);
        float cr0 = exp2f(m[0] - mn0), cr1 = exp2f(m[1] - mn1);
        m[0] = mn0; m[1] = mn1;
        float sum0 = 0.0f, sum1 = 0.0f;
#pragma unroll
        for (int nt = 0; nt < 16; nt++) {
            s[nt][0] = exp2f(s[nt][0] - mn0); sum0 += s[nt][0];
            s[nt][1] = exp2f(s[nt][1] - mn0); sum0 += s[nt][1];
            s[nt][2] = exp2f(s[nt][2] - mn1); sum1 += s[nt][2];
            s[nt][3] = exp2f(s[nt][3] - mn1); sum1 += s[nt][3];
        }
#pragma unroll
        for (int off = 1; off <= 2; off <<= 1) {
            sum0 += __shfl_xor_sync(0xffffffffu, sum0, off, 4);
            sum1 += __shfl_xor_sync(0xffffffffu, sum1, off, 4);
        }
        l[0] = l[0] * cr0 + sum0;
        l[1] = l[1] * cr1 + sum1;
#pragma unroll
        for (int nt = 0; nt < 16; nt++) {
            o[nt][0] *= cr0; o[nt][1] *= cr0;
            o[nt][2] *= cr1; o[nt][3] *= cr1;
        }

        // ---- drain this iteration's V if it was deferred from last iter ----
        if (v_pending) {
            if (prefetched) CP_WAIT(2);   // V(j) done; K(j+1)/V(j+1) may remain
            else            CP_WAIT(0);   // last iteration: drain everything
            __syncthreads();
            v_pending = false;
        }

        // ---- O += P @ V ----
#pragma unroll
        for (int kf = 0; kf < 8; kf++) {
            uint32_t ph[4];
            ph[0] = pack_h2(__float2half_rn(s[2 * kf][0]),     __float2half_rn(s[2 * kf][1]));
            ph[1] = pack_h2(__float2half_rn(s[2 * kf][2]),     __float2half_rn(s[2 * kf][3]));
            ph[2] = pack_h2(__float2half_rn(s[2 * kf + 1][0]), __float2half_rn(s[2 * kf + 1][1]));
            ph[3] = pack_h2(__float2half_rn(s[2 * kf + 1][2]), __float2half_rn(s[2 * kf + 1][3]));
            int r = kf * 16 + (lane & 15);
#pragma unroll
            for (int p = 0; p < 4; p++) {
                int c0 = 4 * p + (lane >> 4);
                int c1 = 4 * p + 2 + (lane >> 4);
                uint32_t v0, v1, v2, v3, u0, u1, u2, u3;
                LDSM4T(v0, v1, v2, v3, ft_addr(sb, 3 + cur, r, c0));
                LDSM4T(u0, u1, u2, u3, ft_addr(sb, 3 + cur, r, c1));
                MMA_F16(o[4 * p],     ph, v0, v1);
                MMA_F16(o[4 * p + 1], ph, v2, v3);
                MMA_F16(o[4 * p + 2], ph, u0, u1);
                MMA_F16(o[4 * p + 3], ph, u2, u3);
            }
        }

        // ---- boundary: wait only for K(j+1); V(j+1) stays in flight ----
        if (prefetched) {
            CP_WAIT(1);            // K group complete (V group may be pending)
            __syncthreads();
            v_pending = true;
        }
    }

    // ---- epilogue: normalize + fp16 store ----
    float inv0 = 1.0f / l[0], inv1 = 1.0f / l[1];
    int row0 = q0 + qw + gid, row1 = row0 + 8;
#pragma unroll
    for (int nt = 0; nt < 16; nt++) {
        int col = nt * 8 + 2 * tig;
        uint32_t h0 = pack_h2(__float2half_rn(o[nt][0] * inv0),
                              __float2half_rn(o[nt][1] * inv0));
        uint32_t h1 = pack_h2(__float2half_rn(o[nt][2] * inv1),
                              __float2half_rn(o[nt][3] * inv1));
        *reinterpret_cast<uint32_t*>(&C1[base + (size_t)row0 * GD + col]) = h0;
        *reinterpret_cast<uint32_t*>(&C1[base + (size_t)row1 * GD + col]) = h1;
    }
}

// ---------------------------------------------------------------------------
extern "C" void kernel_launch(void* const* d_in, const int* in_sizes, int n_in,
                              void* d_out, int out_size)
{
    const float* x  = (const float*)d_in[0];
    const float* Wq = (const float*)d_in[1];
    const float* Wk = (const float*)d_in[2];
    const float* Wv = (const float*)d_in[3];
    const float* Wo = (const float*)d_in[4];

    __half *xh, *ch, *qh, *kh, *vh;
    cudaGetSymbolAddress((void**)&xh, g_xh);
    cudaGetSymbolAddress((void**)&ch, g_ch);
    cudaGetSymbolAddress((void**)&qh, g_qh);
    cudaGetSymbolAddress((void**)&kh, g_kh);
    cudaGetSymbolAddress((void**)&vh, g_vh);

    __half *wq, *wk, *wv, *wo;
    cudaGetSymbolAddress((void**)&wq, g_wq); cudaGetSymbolAddress((void**)&wk, g_wk);
    cudaGetSymbolAddress((void**)&wv, g_wv); cudaGetSymbolAddress((void**)&wo, g_wo);

    cudaFuncSetAttribute(hgemm_qkv, cudaFuncAttributeMaxDynamicSharedMemorySize, GEMM_SMEM);
    cudaFuncSetAttribute(hgemm_out, cudaFuncAttributeMaxDynamicSharedMemorySize, GEMM_SMEM);
    cudaFuncSetAttribute(flash_tc, cudaFuncAttributeMaxDynamicSharedMemorySize, FT_SMEM);

    prep_all<<<dim3(64, 64, 5), dim3(32, 8)>>>(x, xh, Wq, Wk, Wv, Wo, wq, wk, wv, wo);

    dim3 qkv_grid(GD / 128, GM / 128, 3);   // (16, 32, 3)
    hgemm_qkv<<<qkv_grid, 256, GEMM_SMEM>>>(xh, wq, wk, wv, qh, kh, vh);

    flash_tc<<<dim3(SEQ / 128, NH, 2), 256, FT_SMEM>>>(qh, kh, vh, ch);

    dim3 ggrid(GD / 128, GM / 128);         // (16, 32)
    hgemm_out<<<ggrid, 256, GEMM_SMEM>>>(ch, wo, (float*)d_out);
}

// round 17
// speedup vs baseline: 1.0965x; 1.0345x over previous
#include <cuda_runtime.h>
#include <cuda_fp16.h>
#include <math.h>
#include <stdint.h>

// Problem: b=2, s=2048, d=2048, H=16, Dh=128, window=2048 (never binds -> causal)
#define GM 4096
#define GD 2048
#define SEQ 2048
#define NH 16
#define DH 128

// Q is pre-scaled by SM_SCALE*log2(e); softmax runs in exp2 domain.
#define QSCALE (0.08838834764831845f * 1.4426950408889634f)

// ---------------- scratch (device globals; allocation forbidden) ----------------
__device__ __half g_xh[GM * GD];
__device__ __half g_ch[GM * GD];
__device__ __half g_qh[GM * GD];
__device__ __half g_kh[GM * GD];
__device__ __half g_vh[GM * GD];
__device__ __half g_wq[GD * GD], g_wk[GD * GD], g_wv[GD * GD], g_wo[GD * GD];

// ---------------- PTX helpers (compute_103-safe) ----------------
__device__ __forceinline__ uint32_t smem_u32(const void* p) {
    uint32_t a;
    asm("{ .reg .u64 t; cvta.to.shared.u64 t, %1; cvt.u32.u64 %0, t; }" : "=r"(a) : "l"(p));
    return a;
}
#define CP_ASYNC16(dst, src) \
    asm volatile("cp.async.cg.shared.global [%0], [%1], 16;" :: "r"(dst), "l"(src))
#define CP_COMMIT() asm volatile("cp.async.commit_group;" ::: "memory")
#define CP_WAIT(n)  asm volatile("cp.async.wait_group %0;" :: "n"(n) : "memory")

#define LDSM4(r0, r1, r2, r3, addr) \
    asm volatile("ldmatrix.sync.aligned.m8n8.x4.shared.b16 {%0,%1,%2,%3}, [%4];" \
                 : "=r"(r0), "=r"(r1), "=r"(r2), "=r"(r3) : "r"(addr))
#define LDSM4T(r0, r1, r2, r3, addr) \
    asm volatile("ldmatrix.sync.aligned.m8n8.x4.trans.shared.b16 {%0,%1,%2,%3}, [%4];" \
                 : "=r"(r0), "=r"(r1), "=r"(r2), "=r"(r3) : "r"(addr))

#define MMA_F16(d, a, b0, b1)                                               \
    asm volatile(                                                           \
        "mma.sync.aligned.m16n8k16.row.col.f32.f16.f16.f32 "                \
        "{%0,%1,%2,%3}, {%4,%5,%6,%7}, {%8,%9}, {%0,%1,%2,%3};"             \
        : "+f"(d[0]), "+f"(d[1]), "+f"(d[2]), "+f"(d[3])                    \
        : "r"(a[0]), "r"(a[1]), "r"(a[2]), "r"(a[3]), "r"(b0), "r"(b1))

// pack two f32 into f16x2: lo = first arg, hi = second arg
#define CVT2(r, lo, hi) \
    asm("cvt.rn.f16x2.f32 %0, %1, %2;" : "=r"(r) : "f"(hi), "f"(lo))
#define EX2_H2(r) \
    asm("ex2.approx.f16x2 %0, %0;" : "+r"(r))

__device__ __forceinline__ uint32_t pack_h2(__half a, __half b) {
    __half2 t = __halves2half2(a, b);
    return *reinterpret_cast<uint32_t*>(&t);
}

// ---------------------------------------------------------------------------
// Merged prep kernel: z = 0..3 -> transpose+fp16 convert weight z;
//                     z = 4    -> elementwise fp16 convert of x.
// ---------------------------------------------------------------------------
__global__ void prep_all(const float* __restrict__ x, __half* __restrict__ xh,
                         const float* __restrict__ W0, const float* __restrict__ W1,
                         const float* __restrict__ W2, const float* __restrict__ W3,
                         __half* __restrict__ a0, __half* __restrict__ a1,
                         __half* __restrict__ a2, __half* __restrict__ a3)
{
    const int z = blockIdx.z;
    if (z == 4) {
        int blk = blockIdx.y * 64 + blockIdx.x;
        int tid = threadIdx.y * 32 + threadIdx.x;
#pragma unroll
        for (int i = 0; i < 2; i++) {
            int idx = (blk * 512) + tid + i * 256;
            float4 v = reinterpret_cast<const float4*>(x)[idx];
            __half2* p = reinterpret_cast<__half2*>(xh) + 2 * idx;
            p[0] = __halves2half2(__float2half_rn(v.x), __float2half_rn(v.y));
            p[1] = __halves2half2(__float2half_rn(v.z), __float2half_rn(v.w));
        }
        return;
    }
    const float* W = (z == 0) ? W0 : (z == 1) ? W1 : (z == 2) ? W2 : W3;
    __half* o = (z == 0) ? a0 : (z == 1) ? a1 : (z == 2) ? a2 : a3;

    __shared__ float t[32][33];
    const int bx = blockIdx.x * 32;
    const int by = blockIdx.y * 32;
    const int tx = threadIdx.x, ty = threadIdx.y;
#pragma unroll
    for (int i = 0; i < 4; i++)
        t[ty + 8 * i][tx] = W[(size_t)(by + ty + 8 * i) * GD + bx + tx];
    __syncthreads();
#pragma unroll
    for (int i = 0; i < 4; i++)
        o[(size_t)(bx + ty + 8 * i) * GD + by + tx] = __float2half_rn(t[tx][ty + 8 * i]);
}

// ---------------------------------------------------------------------------
// Single-term fp16 GEMM (round-13 proven): 128x128 CTA tile, 256 threads,
// KT=64, 3-stage cp.async pipeline, 96KB smem, 2 CTAs/SM.
// ---------------------------------------------------------------------------
#define KT 64
#define NCH (GD / KT)          // 32
#define TILE_B 16384           // 128 rows * 128 bytes
#define STAGE_B (2 * TILE_B)   // A + B = 32 KB
#define GEMM_SMEM (3 * STAGE_B)

__device__ __forceinline__ void gemm_body(
    const __half* __restrict__ A1, const __half* __restrict__ B1,
    float* __restrict__ Cf, __half* __restrict__ O1,
    float oscale, uint32_t sbase, int m0, int n0)
{
    const int tid  = threadIdx.x;
    const int lane = tid & 31;
    const int warp = tid >> 5;
    const int wm = (warp & 3) * 32;
    const int wn = (warp >> 2) * 64;

    auto load_stage = [&](int ch, int s) {
        const int k0 = ch * KT;
        const uint32_t stage = sbase + s * STAGE_B;
#pragma unroll
        for (int t = 0; t < 2; t++) {
            const __half* gp = (t ? B1 : A1) + (size_t)(t ? n0 : m0) * GD + k0;
#pragma unroll
            for (int i = 0; i < 4; i++) {
                int idx = tid + i * 256;
                int r = idx >> 3, c = idx & 7;
                uint32_t dst = stage + t * TILE_B + r * 128 + ((c ^ (r & 7)) << 4);
                CP_ASYNC16(dst, gp + (size_t)r * GD + c * 8);
            }
        }
        CP_COMMIT();
    };

    float acc[2][8][4];
#pragma unroll
    for (int mt = 0; mt < 2; mt++)
#pragma unroll
        for (int nt = 0; nt < 8; nt++)
#pragma unroll
            for (int r = 0; r < 4; r++) acc[mt][nt][r] = 0.0f;

    load_stage(0, 0);
    load_stage(1, 1);

    for (int ch = 0; ch < NCH; ch++) {
        const int s = ch % 3;
        if (ch + 2 < NCH) { load_stage(ch + 2, (ch + 2) % 3); CP_WAIT(2); }
        else if (ch + 1 < NCH) { CP_WAIT(1); }
        else { CP_WAIT(0); }
        __syncthreads();

        const uint32_t stage = sbase + s * STAGE_B;
#pragma unroll
        for (int ks = 0; ks < 4; ks++) {
            const int chunk = 2 * ks + (lane >> 4);
            uint32_t a1[2][4];
#pragma unroll
            for (int mt = 0; mt < 2; mt++) {
                int row = wm + mt * 16 + (lane & 15);
                LDSM4(a1[mt][0], a1[mt][1], a1[mt][2], a1[mt][3],
                      stage + row * 128 + ((chunk ^ (row & 7)) << 4));
            }
            uint32_t b[8][2];
#pragma unroll
            for (int np = 0; np < 4; np++) {
                int row = wn + np * 16 + (lane & 15);
                uint32_t r0, r1, r2, r3;
                LDSM4(r0, r1, r2, r3,
                      stage + TILE_B + row * 128 + ((chunk ^ (row & 7)) << 4));
                b[2 * np][0] = r0; b[2 * np][1] = r2;
                b[2 * np + 1][0] = r1; b[2 * np + 1][1] = r3;
            }
#pragma unroll
            for (int mt = 0; mt < 2; mt++)
#pragma unroll
                for (int nt = 0; nt < 8; nt++)
                    MMA_F16(acc[mt][nt], a1[mt], b[nt][0], b[nt][1]);
        }
        __syncthreads();
    }

    const int gid = lane >> 2, tig = lane & 3;
#pragma unroll
    for (int mt = 0; mt < 2; mt++)
#pragma unroll
        for (int nt = 0; nt < 8; nt++) {
            int row = m0 + wm + mt * 16 + gid;
            int col = n0 + wn + nt * 8 + tig * 2;
            if (O1) {
                uint32_t h0 = pack_h2(__float2half_rn(acc[mt][nt][0] * oscale),
                                      __float2half_rn(acc[mt][nt][1] * oscale));
                uint32_t h1 = pack_h2(__float2half_rn(acc[mt][nt][2] * oscale),
                                      __float2half_rn(acc[mt][nt][3] * oscale));
                *reinterpret_cast<uint32_t*>(&O1[(size_t)row * GD + col]) = h0;
                *reinterpret_cast<uint32_t*>(&O1[(size_t)(row + 8) * GD + col]) = h1;
            } else {
                *reinterpret_cast<float2*>(&Cf[(size_t)row * GD + col]) =
                    make_float2(acc[mt][nt][0], acc[mt][nt][1]);
                *reinterpret_cast<float2*>(&Cf[(size_t)(row + 8) * GD + col]) =
                    make_float2(acc[mt][nt][2], acc[mt][nt][3]);
            }
        }
}

// Fused Q/K/V projection: single-term. Q output pre-scaled by QSCALE.
__global__ __launch_bounds__(256, 2) void hgemm_qkv(
    const __half* __restrict__ xh,
    const __half* __restrict__ wq, const __half* __restrict__ wk,
    const __half* __restrict__ wv,
    __half* __restrict__ qh, __half* __restrict__ kh, __half* __restrict__ vh)
{
    extern __shared__ char smem[];
    const int z = blockIdx.z;
    const __half* B1 = (z == 0) ? wq : (z == 1) ? wk : wv;
    __half* O1 = (z == 0) ? qh : (z == 1) ? kh : vh;
    float oscale = (z == 0) ? QSCALE : 1.0f;
    gemm_body(xh, B1, nullptr, O1, oscale,
              smem_u32(smem), blockIdx.y * 128, blockIdx.x * 128);
}

// Output projection: single-term, fp32 result.
__global__ __launch_bounds__(256, 2) void hgemm_out(
    const __half* __restrict__ ch, const __half* __restrict__ wo,
    float* __restrict__ Cf)
{
    extern __shared__ char smem[];
    gemm_body(ch, wo, Cf, nullptr, 1.0f,
              smem_u32(smem), blockIdx.y * 128, blockIdx.x * 128);
}

// ---------------------------------------------------------------------------
// Flash attention v4 (round-13 flow): exp2 softmax in fp16 via
// ex2.approx.f16x2; row sums l computed on the tensor pipe with a ones-B MMA
// (exact fp32 sum of the quantized P, consistent with PV). Single K+V
// prefetch group per iteration (round-13 proven).
// smem tiles (32KB): 0 Qh, 1/2 Kh[buf], 3/4 Vh[buf] = 160KB.
// ---------------------------------------------------------------------------
#define FT_TILE 32768
#define FT_SMEM (5 * FT_TILE)

__device__ __forceinline__ uint32_t ft_addr(uint32_t sb, int tile, int r, int c) {
    return sb + tile * FT_TILE + r * 256 + (((c & 8) | ((c ^ (r & 7)) & 7)) << 4);
}

__global__ __launch_bounds__(256, 1) void flash_tc(
    const __half* __restrict__ Qh, const __half* __restrict__ Kh,
    const __half* __restrict__ Vh, __half* __restrict__ C1)
{
    extern __shared__ char smem[];
    const uint32_t sb = smem_u32(smem);

    const int tid = threadIdx.x, lane = tid & 31, warp = tid >> 5;
    const int qt = gridDim.x - 1 - blockIdx.x;   // heavy tiles first
    const int h = blockIdx.y, b = blockIdx.z;
    const int q0 = qt * 128;
    const size_t base = ((size_t)b * SEQ) * GD + (size_t)h * DH;

    auto load_tile = [&](int t, const __half* src, int r0) {
        const __half* g = src + base + (size_t)r0 * GD;
#pragma unroll
        for (int i = 0; i < 8; i++) {
            int idx = tid + i * 256;
            int r = idx >> 4, c = idx & 15;
            CP_ASYNC16(ft_addr(sb, t, r, c), g + (size_t)r * GD + c * 8);
        }
    };

    load_tile(0, Qh, q0);
    load_tile(1, Kh, 0);
    load_tile(3, Vh, 0);
    CP_COMMIT(); CP_WAIT(0); __syncthreads();

    const int gid = lane >> 2, tig = lane & 3;
    const int qw = warp * 16;
    const uint32_t ONE2 = 0x3C003C00u;   // {1.0h, 1.0h}

    float o[16][4];
#pragma unroll
    for (int nt = 0; nt < 16; nt++)
#pragma unroll
        for (int c = 0; c < 4; c++) o[nt][c] = 0.0f;
    float m[2] = {-1e30f, -1e30f}, l[2] = {0.0f, 0.0f};

    for (int jt = 0; jt <= qt; jt++) {
        const int cur = jt & 1, nxt = cur ^ 1;

        // ---- S = Q @ K^T (single term) ----
        float s[16][4];
#pragma unroll
        for (int nt = 0; nt < 16; nt++)
#pragma unroll
            for (int c = 0; c < 4; c++) s[nt][c] = 0.0f;

#pragma unroll
        for (int kf = 0; kf < 8; kf++) {
            const int ac = 2 * kf + (lane >> 4);
            uint32_t ah[4];
            {
                int r = qw + (lane & 15);
                LDSM4(ah[0], ah[1], ah[2], ah[3], ft_addr(sb, 0, r, ac));
            }
#pragma unroll
            for (int p = 0; p < 4; p++) {
                int r0 = (2 * p) * 16 + (lane & 15);
                int r1 = (2 * p + 1) * 16 + (lane & 15);
                uint32_t h0, h1, h2, h3, i0, i1, i2, i3;
                LDSM4(h0, h1, h2, h3, ft_addr(sb, 1 + cur, r0, ac));
                LDSM4(i0, i1, i2, i3, ft_addr(sb, 1 + cur, r1, ac));
                MMA_F16(s[4 * p],     ah, h0, h2);
                MMA_F16(s[4 * p + 1], ah, h1, h3);
                MMA_F16(s[4 * p + 2], ah, i0, i2);
                MMA_F16(s[4 * p + 3], ah, i1, i3);
            }
        }

        // early prefetch of next K/V (disjoint buffer) — overlaps softmax too
        const bool prefetched = (jt < qt);
        if (prefetched) {
            load_tile(1 + nxt, Kh, (jt + 1) * 128);
            load_tile(3 + nxt, Vh, (jt + 1) * 128);
            CP_COMMIT();
        }

        // ---- causal mask (diag tile only) ----
        if (jt == qt) {
#pragma unroll
            for (int nt = 0; nt < 16; nt++) {
                int colb = jt * 128 + nt * 8 + 2 * tig;
#pragma unroll
                for (int c = 0; c < 4; c++) {
                    int row = q0 + qw + gid + ((c >= 2) ? 8 : 0);
                    int col = colb + (c & 1);
                    if (col > row) s[nt][c] = -1e30f;
                }
            }
        }

        // ---- row max (fp32) ----
        float mx0 = -1e30f, mx1 = -1e30f;
#pragma unroll
        for (int nt = 0; nt < 16; nt++) {
            mx0 = fmaxf(mx0, fmaxf(s[nt][0], s[nt][1]));
            mx1 = fmaxf(mx1, fmaxf(s[nt][2], s[nt][3]));
        }
#pragma unroll
        for (int off = 1; off <= 2; off <<= 1) {
            mx0 = fmaxf(mx0, __shfl_xor_sync(0xffffffffu, mx0, off, 4));
            mx1 = fmaxf(mx1, __shfl_xor_sync(0xffffffffu, mx1, off, 4));
        }
        float mn0 = fmaxf(m[0], mx0), mn1 = fmaxf(m[1], mx1);
        float cr0 = exp2f(m[0] - mn0), cr1 = exp2f(m[1] - mn1);
        m[0] = mn0; m[1] = mn1;

        // ---- P = exp2(s - mn) directly in fp16 (ex2.approx.f16x2) ----
        uint32_t P[8][4];
#pragma unroll
        for (int kf = 0; kf < 8; kf++) {
            CVT2(P[kf][0], s[2 * kf][0] - mn0,     s[2 * kf][1] - mn0);
            CVT2(P[kf][1], s[2 * kf][2] - mn1,     s[2 * kf][3] - mn1);
            CVT2(P[kf][2], s[2 * kf + 1][0] - mn0, s[2 * kf + 1][1] - mn0);
            CVT2(P[kf][3], s[2 * kf + 1][2] - mn1, s[2 * kf + 1][3] - mn1);
            EX2_H2(P[kf][0]); EX2_H2(P[kf][1]);
            EX2_H2(P[kf][2]); EX2_H2(P[kf][3]);
        }

        // ---- l row-sums via ones-B MMA (exact fp32 sum of quantized P) ----
        float lsum[4] = {0.0f, 0.0f, 0.0f, 0.0f};
#pragma unroll
        for (int kf = 0; kf < 8; kf++)
            MMA_F16(lsum, P[kf], ONE2, ONE2);
        l[0] = l[0] * cr0 + lsum[0];
        l[1] = l[1] * cr1 + lsum[2];

        // ---- rescale O ----
#pragma unroll
        for (int nt = 0; nt < 16; nt++) {
            o[nt][0] *= cr0; o[nt][1] *= cr0;
            o[nt][2] *= cr1; o[nt][3] *= cr1;
        }

        // ---- O += P @ V ----
#pragma unroll
        for (int kf = 0; kf < 8; kf++) {
            int r = kf * 16 + (lane & 15);
#pragma unroll
            for (int p = 0; p < 4; p++) {
                int c0 = 4 * p + (lane >> 4);
                int c1 = 4 * p + 2 + (lane >> 4);
                uint32_t v0, v1, v2, v3, u0, u1, u2, u3;
                LDSM4T(v0, v1, v2, v3, ft_addr(sb, 3 + cur, r, c0));
                LDSM4T(u0, u1, u2, u3, ft_addr(sb, 3 + cur, r, c1));
                MMA_F16(o[4 * p],     P[kf], v0, v1);
                MMA_F16(o[4 * p + 1], P[kf], v2, v3);
                MMA_F16(o[4 * p + 2], P[kf], u0, u1);
                MMA_F16(o[4 * p + 3], P[kf], u2, u3);
            }
        }

        if (prefetched) { CP_WAIT(0); __syncthreads(); }   // one sync per k-tile
    }

    // ---- epilogue: normalize + fp16 store ----
    float inv0 = 1.0f / l[0], inv1 = 1.0f / l[1];
    int row0 = q0 + qw + gid, row1 = row0 + 8;
#pragma unroll
    for (int nt = 0; nt < 16; nt++) {
        int col = nt * 8 + 2 * tig;
        uint32_t h0, h1;
        CVT2(h0, o[nt][0] * inv0, o[nt][1] * inv0);
        CVT2(h1, o[nt][2] * inv1, o[nt][3] * inv1);
        *reinterpret_cast<uint32_t*>(&C1[base + (size_t)row0 * GD + col]) = h0;
        *reinterpret_cast<uint32_t*>(&C1[base + (size_t)row1 * GD + col]) = h1;
    }
}

// ---------------------------------------------------------------------------
extern "C" void kernel_launch(void* const* d_in, const int* in_sizes, int n_in,
                              void* d_out, int out_size)
{
    const float* x  = (const float*)d_in[0];
    const float* Wq = (const float*)d_in[1];
    const float* Wk = (const float*)d_in[2];
    const float* Wv = (const float*)d_in[3];
    const float* Wo = (const float*)d_in[4];

    __half *xh, *ch, *qh, *kh, *vh;
    cudaGetSymbolAddress((void**)&xh, g_xh);
    cudaGetSymbolAddress((void**)&ch, g_ch);
    cudaGetSymbolAddress((void**)&qh, g_qh);
    cudaGetSymbolAddress((void**)&kh, g_kh);
    cudaGetSymbolAddress((void**)&vh, g_vh);

    __half *wq, *wk, *wv, *wo;
    cudaGetSymbolAddress((void**)&wq, g_wq); cudaGetSymbolAddress((void**)&wk, g_wk);
    cudaGetSymbolAddress((void**)&wv, g_wv); cudaGetSymbolAddress((void**)&wo, g_wo);

    cudaFuncSetAttribute(hgemm_qkv, cudaFuncAttributeMaxDynamicSharedMemorySize, GEMM_SMEM);
    cudaFuncSetAttribute(hgemm_out, cudaFuncAttributeMaxDynamicSharedMemorySize, GEMM_SMEM);
    cudaFuncSetAttribute(flash_tc, cudaFuncAttributeMaxDynamicSharedMemorySize, FT_SMEM);

    prep_all<<<dim3(64, 64, 5), dim3(32, 8)>>>(x, xh, Wq, Wk, Wv, Wo, wq, wk, wv, wo);

    dim3 qkv_grid(GD / 128, GM / 128, 3);   // (16, 32, 3)
    hgemm_qkv<<<qkv_grid, 256, GEMM_SMEM>>>(xh, wq, wk, wv, qh, kh, vh);

    flash_tc<<<dim3(SEQ / 128, NH, 2), 256, FT_SMEM>>>(qh, kh, vh, ch);

    dim3 ggrid(GD / 128, GM / 128);         // (16, 32)
    hgemm_out<<<ggrid, 256, GEMM_SMEM>>>(ch, wo, (float*)d_out);
}